// round 17
// baseline (speedup 1.0000x reference)
#include <cuda_runtime.h>

#define NB    2048
#define NE    30
#define NA    38
#define NN    8
#define BASIS 32
#define KD    64
#define ED    128
#define HK    45
#define HO    91
#define NL    3

typedef unsigned long long ull;
typedef unsigned int uint32;

__device__ float g_xs [NB * NE * ED];

// Prepacked tf32 B-fragments, kt-PAIR packed (uint4 = two mma B operands).
// B1f: sigma-permuted K (fragment (kt,t) -> w1 rows {4t+kt, 16+4t+kt}).
// B2f: sigma2-permuted K (step s: pos t -> w2 row 8s+2t; pos t+4 -> 8s+2t+1),
//      so GEMM2's A comes straight from GEMM1's D registers. Row 45 = b2.
__device__ uint4 g_B1f[NL][6 * 2 * 32];     // msg w1  [nt6][kt2:2][lane]
__device__ uint4 g_B2f[NL][8 * 3 * 32];     // msg w2 + b2 row45 [nt8][kt2:3][lane]
__device__ uint4 g_B1o[NL][12 * 4 * 32];    // out W1  [nt12][kt2:4][lane]
__device__ uint4 g_B2o[NL][16 * 6 * 32];    // out W2  [nt16][kt2:6][lane]
__device__ uint4 g_BeH[NL][8 * 8 * 32];     // eiw hi  [nt8][kt2:8][lane]
__device__ uint4 g_BeL[NL][8 * 8 * 32];     // eiw lo  [nt8][kt2:8][lane]

__device__ __forceinline__ float ssp(float x) {
    float t = __expf(-fabsf(x));
    return fmaxf(x, 0.f) + __logf(1.f + t) - 0.69314718055994530942f;
}
__device__ __forceinline__ void sts2(float* p, float x, float y) {
    *reinterpret_cast<float2*>(p) = make_float2(x, y);
}
__device__ __forceinline__ uint32 f2tf(float x) {
    uint32 u; asm("cvt.rna.tf32.f32 %0, %1;" : "=r"(u) : "f"(x)); return u;
}
__device__ __forceinline__ void mma8(float& d0, float& d1, float& d2, float& d3,
                                     uint32 a0, uint32 a1, uint32 a2, uint32 a3,
                                     uint32 b0, uint32 b1) {
    asm volatile(
        "mma.sync.aligned.m16n8k8.row.col.f32.tf32.tf32.f32 "
        "{%0,%1,%2,%3},{%4,%5,%6,%7},{%8,%9},{%0,%1,%2,%3};"
        : "+f"(d0), "+f"(d1), "+f"(d2), "+f"(d3)
        : "r"(a0), "r"(a1), "r"(a2), "r"(a3), "r"(b0), "r"(b1));
}

__global__ void k_init(const float* __restrict__ emb_elec) {
    const int total = NB * NE * ED;
    for (int idx = blockIdx.x * blockDim.x + threadIdx.x; idx < total;
         idx += gridDim.x * blockDim.x) {
        int d = idx % ED, i = (idx / ED) % NE;
        g_xs[idx] = emb_elec[i * ED + d];
    }
}

// ---------------------------------------------------------------------------
// One-time fragment prepack: block l handles layer l.
// ---------------------------------------------------------------------------
__global__ void k_prepack(const float* __restrict__ kw1,
                          const float* __restrict__ kw2,
                          const float* __restrict__ kb2,
                          const float* __restrict__ ow1,
                          const float* __restrict__ ow2,
                          const float* __restrict__ eiw) {
    const int l = blockIdx.x, tid = threadIdx.x;
    const float* w1 = kw1 + (size_t)l * BASIS * HK;
    const float* w2 = kw2 + (size_t)l * HK * KD;
    const float* b2 = kb2 + (size_t)l * KD;
    const float* W1 = ow1 + (size_t)l * KD * HO;
    const float* W2 = ow2 + (size_t)l * HO * ED;
    const float* We = eiw + (size_t)l * ED * KD;

    // B1f with sigma-permuted K for coalesced float4 A-loads
    for (int it = tid; it < 6 * 2 * 32; it += 256) {
        int lane_ = it & 31;
        int kt2 = (it >> 5) & 1;
        int nt  = it >> 6;
        int g_ = lane_ >> 2, t_ = lane_ & 3;
        int n  = nt * 8 + g_;
        bool ok = (n < HK);
        int kt0 = 2 * kt2, kt1 = kt0 + 1;
        g_B1f[l][it] = make_uint4(
            f2tf(ok ? w1[(4 * t_ + kt0) * HK + n] : 0.f),
            f2tf(ok ? w1[(16 + 4 * t_ + kt0) * HK + n] : 0.f),
            f2tf(ok ? w1[(4 * t_ + kt1) * HK + n] : 0.f),
            f2tf(ok ? w1[(16 + 4 * t_ + kt1) * HK + n] : 0.f));
    }
    // B2f sigma2: step s, pos t -> k = 8s + 2t; pos t+4 -> k = 8s + 2t + 1.
    // uint4: x = step 2kt2 pos t (k00), y = step 2kt2 pos t+4 (k00+1),
    //        z = step 2kt2+1 pos t (k10), w = step 2kt2+1 pos t+4 (k10+1)
    for (int it = tid; it < 8 * 3 * 32; it += 256) {
        int lane_ = it & 31;
        int kt2 = (it >> 5) % 3;
        int nt  = it / 96;
        int g_ = lane_ >> 2, t_ = lane_ & 3;
        int n  = nt * 8 + g_;
        int k00 = 8 * (2 * kt2) + 2 * t_;       // step 2kt2, pos t
        int k10 = 8 * (2 * kt2 + 1) + 2 * t_;   // step 2kt2+1, pos t
        float v[4];
        int ks[4] = { k00, k00 + 1, k10, k10 + 1 };
        #pragma unroll
        for (int m = 0; m < 4; ++m) {
            int k = ks[m];
            v[m] = (k < HK) ? w2[k * KD + n] : ((k == HK) ? b2[n] : 0.f);
        }
        g_B2f[l][it] = make_uint4(f2tf(v[0]), f2tf(v[1]), f2tf(v[2]), f2tf(v[3]));
    }
    for (int it = tid; it < 12 * 4 * 32; it += 256) {
        int lane_ = it & 31;
        int kt2 = (it >> 5) & 3;
        int nt  = it >> 7;
        int g_ = lane_ >> 2, t_ = lane_ & 3;
        int n  = nt * 8 + g_;
        int ka = kt2 * 16 + t_;
        bool ok = (n < HO);
        g_B1o[l][it] = make_uint4(f2tf(ok ? W1[ka * HO + n] : 0.f),
                                  f2tf(ok ? W1[(ka + 4) * HO + n] : 0.f),
                                  f2tf(ok ? W1[(ka + 8) * HO + n] : 0.f),
                                  f2tf(ok ? W1[(ka + 12) * HO + n] : 0.f));
    }
    for (int it = tid; it < 16 * 6 * 32; it += 256) {
        int lane_ = it & 31;
        int kt2 = (it >> 5) % 6;
        int nt  = it / 192;
        int g_ = lane_ >> 2, t_ = lane_ & 3;
        int n  = nt * 8 + g_;
        int ka = kt2 * 16 + t_;
        g_B2o[l][it] = make_uint4(
            f2tf((ka      < HO) ? W2[ka * ED + n] : 0.f),
            f2tf((ka + 4  < HO) ? W2[(ka + 4) * ED + n] : 0.f),
            f2tf((ka + 8  < HO) ? W2[(ka + 8) * ED + n] : 0.f),
            f2tf((ka + 12 < HO) ? W2[(ka + 12) * ED + n] : 0.f));
    }
    // eiw hi/lo split fragments (K=128 -> 8 kt2, N=64 -> 8 nt)
    for (int it = tid; it < 8 * 8 * 32; it += 256) {
        int lane_ = it & 31;
        int kt2 = (it >> 5) & 7;
        int nt  = it >> 8;
        int g_ = lane_ >> 2, t_ = lane_ & 3;
        int n  = nt * 8 + g_;
        int ka = kt2 * 16 + t_;
        uint32 h[4], lo[4];
        #pragma unroll
        for (int m = 0; m < 4; ++m) {
            float v = We[(ka + 4 * m) * KD + n];
            h[m]  = f2tf(v);
            lo[m] = f2tf(v - __uint_as_float(h[m]));
        }
        g_BeH[l][it] = make_uint4(h[0], h[1], h[2], h[3]);
        g_BeL[l][it] = make_uint4(lo[0], lo[1], lo[2], lo[3]);
    }
}

// ---------------------------------------------------------------------------
// k_layer = zs (3xTF32 MMA) + msg (pair MLP, MMA, register-resident H)
//           + fused out MLP (MMA).
// smem (floats):
//   zsv   [0,3456)       zs[j][c], j 0..47 (38..47 zero), stride 72
//   smsg  [3456,5632)    32 rows x stride 68 (rows>=30 zero)
//   scratch [5632,10240) (4608 floats)
//     phase1: xs2 30x132 (3960 f)
//     phase2: B1f uint4[384] | B2f uint4[768] @+1536
//     out:    Hs 32x100 (3200 f)
//   sb1 [10240,10288) | sb1o [10288,10384) | sb2o [10384,10512)
// ---------------------------------------------------------------------------
#define MS_TOTAL_F 10512
#define MS_BYTES   (MS_TOTAL_F * 4)

__global__ void __launch_bounds__(256, 3) k_layer(
        const float* __restrict__ dists,
        const float* __restrict__ emb_nuc,
        const float* __restrict__ kb1,
        const float* __restrict__ ob1,
        const float* __restrict__ ob2,
        int l, float* __restrict__ xs_out) {
    extern __shared__ float sm[];
    float*  zsv     = sm;
    float*  smsg    = sm + 3456;
    float*  scratch = sm + 5632;
    float*  xs2     = scratch;
    uint4*  B1f     = reinterpret_cast<uint4*>(scratch);           // 384 uint4
    uint4*  B2f     = reinterpret_cast<uint4*>(scratch + 1536);    // 768 uint4
    uint32* Hs      = reinterpret_cast<uint32*>(scratch);
    float*  sb1     = sm + 10240;
    float*  sb1o    = sm + 10288;
    float*  sb2o    = sm + 10384;

    const int b = blockIdx.x, tid = threadIdx.x;
    const int w = tid >> 5, lane = tid & 31;
    const int g = lane >> 2, t = lane & 3;

    // ---- phase 1a: stage xs (stride 132), nuclear zs, pads, biases ----
    {
        const float* xsb = g_xs + (size_t)b * NE * ED;
        for (int it = tid; it < NE * 64; it += 256) {
            int r = it >> 6, c2 = it & 63;
            float2 v = *reinterpret_cast<const float2*>(xsb + r * ED + 2 * c2);
            *reinterpret_cast<float2*>(xs2 + r * 132 + 2 * c2) = v;
        }
        for (int idx = tid; idx < NN * KD; idx += 256) {
            int n = idx >> 6, c = idx & 63;
            zsv[(NE + n) * 72 + c] = emb_nuc[n * KD + c];
        }
        for (int idx = tid; idx < 10 * 64; idx += 256) {
            int r = idx >> 6, c = idx & 63;
            zsv[(38 + r) * 72 + c] = 0.f;
        }
        for (int idx = tid; idx < 2 * 68; idx += 256)
            smsg[30 * 68 + idx] = 0.f;
        if (tid < 48)  sb1[tid]  = (tid < HK) ? kb1[l * HK + tid] : 0.f;
        if (tid < 96)  sb1o[tid] = (tid < HO) ? ob1[l * HO + tid] : 0.f;
        if (tid < 128) sb2o[tid] = ob2[l * ED + tid];
    }
    __syncthreads();

    // ---- phase 1b: electron zs = xs @ eiw via 3xTF32 MMA (warp w -> nt=w) ----
    {
        float D0[4] = {0.f, 0.f, 0.f, 0.f};
        float D1[4] = {0.f, 0.f, 0.f, 0.f};
        #pragma unroll
        for (int kt2 = 0; kt2 < 8; ++kt2) {
            uint4 bh = __ldg(g_BeH[l] + (w * 8 + kt2) * 32 + lane);
            uint4 bl = __ldg(g_BeL[l] + (w * 8 + kt2) * 32 + lane);
            #pragma unroll
            for (int h = 0; h < 2; ++h) {
                int c = (kt2 * 2 + h) * 8 + t;
                uint32 bx = h ? bh.z : bh.x, by = h ? bh.w : bh.y;
                uint32 lx = h ? bl.z : bl.x, ly = h ? bl.w : bl.y;
                #pragma unroll
                for (int mt = 0; mt < 2; ++mt) {
                    int r0 = mt * 16 + g, r1 = r0 + 8;
                    float x0 = (r0 < NE) ? xs2[r0 * 132 + c] : 0.f;
                    float x1 = (r1 < NE) ? xs2[r1 * 132 + c] : 0.f;
                    float x2 = (r0 < NE) ? xs2[r0 * 132 + c + 4] : 0.f;
                    float x3 = (r1 < NE) ? xs2[r1 * 132 + c + 4] : 0.f;
                    uint32 a0 = f2tf(x0), a1 = f2tf(x1), a2 = f2tf(x2), a3 = f2tf(x3);
                    uint32 e0 = f2tf(x0 - __uint_as_float(a0));
                    uint32 e1 = f2tf(x1 - __uint_as_float(a1));
                    uint32 e2 = f2tf(x2 - __uint_as_float(a2));
                    uint32 e3 = f2tf(x3 - __uint_as_float(a3));
                    float* D = mt ? D1 : D0;
                    mma8(D[0], D[1], D[2], D[3], a0, a1, a2, a3, bx, by);
                    mma8(D[0], D[1], D[2], D[3], a0, a1, a2, a3, lx, ly);
                    mma8(D[0], D[1], D[2], D[3], e0, e1, e2, e3, bx, by);
                }
            }
        }
        #pragma unroll
        for (int mt = 0; mt < 2; ++mt) {
            int r0 = mt * 16 + g, r1 = r0 + 8;
            float* D = mt ? D1 : D0;
            if (r0 < NE) sts2(zsv + r0 * 72 + w * 8 + 2 * t, D[0], D[1]);
            if (r1 < NE) sts2(zsv + r1 * 72 + w * 8 + 2 * t, D[2], D[3]);
        }
    }
    __syncthreads();

    // ---- phase 2a: copy prepacked msg B-fragments into smem (uint4) ----
    {
        const uint4* s1 = g_B1f[l];
        for (int it = tid; it < 384; it += 256) B1f[it] = s1[it];
        const uint4* s2 = g_B2f[l];
        for (int it = tid; it < 768; it += 256) B2f[it] = s2[it];
    }
    __syncthreads();

    // ---- main loop: pair MLP + j-sum -> smsg (H stays in registers) ----
    for (int i = w; i < NE; i += 8) {
        const float* dbase = dists + ((size_t)(b * NE + i)) * NA * BASIS;
        float macc[16];
        #pragma unroll
        for (int r = 0; r < 16; ++r) macc[r] = 0.f;

        #pragma unroll
        for (int mt = 0; mt < 3; ++mt) {
            const int j0 = mt * 16 + g, j1 = j0 + 8;

            // A1 via coalesced float4 loads (sigma-permuted K, matches B1f)
            const float4 zf4 = make_float4(0.f, 0.f, 0.f, 0.f);
            float4 l0 = (j0 < NA) ? __ldg(reinterpret_cast<const float4*>(dbase + j0 * BASIS + 4 * t)) : zf4;
            float4 h0 = (j0 < NA) ? __ldg(reinterpret_cast<const float4*>(dbase + j0 * BASIS + 16 + 4 * t)) : zf4;
            float4 l1 = (j1 < NA) ? __ldg(reinterpret_cast<const float4*>(dbase + j1 * BASIS + 4 * t)) : zf4;
            float4 h1 = (j1 < NA) ? __ldg(reinterpret_cast<const float4*>(dbase + j1 * BASIS + 16 + 4 * t)) : zf4;
            const float* pl0 = reinterpret_cast<const float*>(&l0);
            const float* ph0 = reinterpret_cast<const float*>(&h0);
            const float* pl1 = reinterpret_cast<const float*>(&l1);
            const float* ph1 = reinterpret_cast<const float*>(&h1);
            uint32 A1[4][4];
            #pragma unroll
            for (int kt = 0; kt < 4; ++kt) {
                A1[kt][0] = f2tf(pl0[kt]);
                A1[kt][1] = f2tf(pl1[kt]);
                A1[kt][2] = f2tf(ph0[kt]);
                A1[kt][3] = f2tf(ph1[kt]);
            }

            // GEMM1; D fragments become GEMM2 A fragments directly (sigma2)
            uint32 A2[6][4];
            #pragma unroll
            for (int nt = 0; nt < 6; ++nt) {
                float2 bb = *reinterpret_cast<const float2*>(sb1 + nt * 8 + 2 * t);
                float d0 = bb.x, d1 = bb.y, d2 = bb.x, d3 = bb.y;
                const uint4* bp = B1f + nt * 64 + lane;
                #pragma unroll
                for (int kt2 = 0; kt2 < 2; ++kt2) {
                    uint4 bf = bp[kt2 * 32];
                    mma8(d0, d1, d2, d3,
                         A1[2 * kt2][0], A1[2 * kt2][1], A1[2 * kt2][2], A1[2 * kt2][3],
                         bf.x, bf.y);
                    mma8(d0, d1, d2, d3,
                         A1[2 * kt2 + 1][0], A1[2 * kt2 + 1][1], A1[2 * kt2 + 1][2], A1[2 * kt2 + 1][3],
                         bf.z, bf.w);
                }
                // A2[step nt] = (H[g][8nt+2t], H[g+8][8nt+2t],
                //                H[g][8nt+2t+1], H[g+8][8nt+2t+1])
                uint32 s0  = f2tf(ssp(d0));
                uint32 s1v = f2tf(ssp(d1));
                uint32 s2  = f2tf(ssp(d2));
                uint32 s3  = f2tf(ssp(d3));
                if (nt == 5 && t == 2) {   // H col 45 := 1.0 (bias K-row)
                    s1v = 0x3f800000u;
                    s3  = 0x3f800000u;
                }
                A2[nt][0] = s0;
                A2[nt][1] = s2;
                A2[nt][2] = s1v;
                A2[nt][3] = s3;
            }

            const float pm0 = (j0 != i) ? 1.f : 0.f;
            const float pm1 = (j1 != i) ? 1.f : 0.f;

            // GEMM2 (sigma2 K-order) + zs multiply + accumulate
            #pragma unroll
            for (int nt = 0; nt < 8; ++nt) {
                float d0 = 0.f, d1 = 0.f, d2 = 0.f, d3 = 0.f;   // bias via K-row 45
                const uint4* bp = B2f + nt * 96 + lane;
                #pragma unroll
                for (int kt2 = 0; kt2 < 3; ++kt2) {
                    uint4 bf = bp[kt2 * 32];
                    mma8(d0, d1, d2, d3,
                         A2[2 * kt2][0], A2[2 * kt2][1], A2[2 * kt2][2], A2[2 * kt2][3],
                         bf.x, bf.y);
                    mma8(d0, d1, d2, d3,
                         A2[2 * kt2 + 1][0], A2[2 * kt2 + 1][1], A2[2 * kt2 + 1][2], A2[2 * kt2 + 1][3],
                         bf.z, bf.w);
                }
                float2 z0 = *reinterpret_cast<const float2*>(zsv + j0 * 72 + nt * 8 + 2 * t);
                float2 z1 = *reinterpret_cast<const float2*>(zsv + j1 * 72 + nt * 8 + 2 * t);
                macc[2 * nt]     += pm0 * d0 * z0.x + pm1 * d2 * z1.x;
                macc[2 * nt + 1] += pm0 * d1 * z0.y + pm1 * d3 * z1.y;
            }
        }

        #pragma unroll
        for (int r = 0; r < 16; ++r) {
            macc[r] += __shfl_xor_sync(0xffffffffu, macc[r], 4);
            macc[r] += __shfl_xor_sync(0xffffffffu, macc[r], 8);
            macc[r] += __shfl_xor_sync(0xffffffffu, macc[r], 16);
        }
        if (g == 0) {
            #pragma unroll
            for (int nt = 0; nt < 8; ++nt)
                sts2(smsg + i * 68 + nt * 8 + 2 * t, macc[2 * nt], macc[2 * nt + 1]);
        }
    }
    __syncthreads();   // smsg complete; scratch (B1f/B2f) now dead

    // ---- out GEMM1: Hs = ssp(msg @ W1 + b1); warp covers nt = w, w+8 ----
    #pragma unroll
    for (int mt = 0; mt < 2; ++mt) {
        int r0 = (mt * 16 + g) * 68, r1 = (mt * 16 + g + 8) * 68;
        #pragma unroll
        for (int rep = 0; rep < 2; ++rep) {
            int nt = w + 8 * rep;
            if (nt < 12) {
                float2 bb = *reinterpret_cast<const float2*>(sb1o + nt * 8 + 2 * t);
                float d0 = bb.x, d1 = bb.y, d2 = bb.x, d3 = bb.y;
                const uint4* bp = g_B1o[l] + nt * 128 + lane;
                #pragma unroll
                for (int kt2 = 0; kt2 < 4; ++kt2) {
                    uint4 bf = __ldg(bp + kt2 * 32);
                    #pragma unroll
                    for (int h = 0; h < 2; ++h) {
                        int kt = 2 * kt2 + h;
                        int c = kt * 8 + t;
                        uint32 a0 = f2tf(smsg[r0 + c]);
                        uint32 a1 = f2tf(smsg[r1 + c]);
                        uint32 a2 = f2tf(smsg[r0 + c + 4]);
                        uint32 a3 = f2tf(smsg[r1 + c + 4]);
                        mma8(d0, d1, d2, d3, a0, a1, a2, a3,
                             h ? bf.z : bf.x, h ? bf.w : bf.y);
                    }
                }
                int c = nt * 8 + 2 * t;
                *reinterpret_cast<uint2*>(Hs + (mt * 16 + g) * 100 + c) =
                    make_uint2(f2tf(ssp(d0)), f2tf(ssp(d1)));
                *reinterpret_cast<uint2*>(Hs + (mt * 16 + g + 8) * 100 + c) =
                    make_uint2(f2tf(ssp(d2)), f2tf(ssp(d3)));
            }
        }
    }
    __syncthreads();

    // ---- out GEMM2 + residual: xs_out = xs + Hs @ W2 + b2; nt = 2w, 2w+1 ----
    #pragma unroll
    for (int mt = 0; mt < 2; ++mt) {
        int r0 = (mt * 16 + g) * 100, r1 = (mt * 16 + g + 8) * 100;
        int e0 = mt * 16 + g, e1 = e0 + 8;
        #pragma unroll
        for (int idx = 0; idx < 2; ++idx) {
            int nt = 2 * w + idx;
            float2 bb = *reinterpret_cast<const float2*>(sb2o + nt * 8 + 2 * t);
            float d0 = bb.x, d1 = bb.y, d2 = bb.x, d3 = bb.y;
            const uint4* bp = g_B2o[l] + nt * 192 + lane;
            #pragma unroll
            for (int kt2 = 0; kt2 < 6; ++kt2) {
                uint4 bf = __ldg(bp + kt2 * 32);
                #pragma unroll
                for (int h = 0; h < 2; ++h) {
                    int kt = 2 * kt2 + h;
                    int c = kt * 8 + t;
                    mma8(d0, d1, d2, d3,
                         Hs[r0 + c], Hs[r1 + c], Hs[r0 + c + 4], Hs[r1 + c + 4],
                         h ? bf.z : bf.x, h ? bf.w : bf.y);
                }
            }
            int c = nt * 8 + 2 * t;
            if (e0 < NE) {
                size_t o = ((size_t)(b * NE + e0)) * ED + c;
                float2 xv = *reinterpret_cast<const float2*>(g_xs + o);
                *reinterpret_cast<float2*>(xs_out + o) =
                    make_float2(xv.x + d0, xv.y + d1);
            }
            if (e1 < NE) {
                size_t o = ((size_t)(b * NE + e1)) * ED + c;
                float2 xv = *reinterpret_cast<const float2*>(g_xs + o);
                *reinterpret_cast<float2*>(xs_out + o) =
                    make_float2(xv.x + d2, xv.y + d3);
            }
        }
    }
}

// ---------------------------------------------------------------------------
extern "C" void kernel_launch(void* const* d_in, const int* in_sizes, int n_in,
                              void* d_out, int out_size) {
    const float* dists    = (const float*)d_in[0];
    const float* emb_elec = (const float*)d_in[1];
    const float* emb_nuc  = (const float*)d_in[2];
    const float* kw1      = (const float*)d_in[3];
    const float* kb1      = (const float*)d_in[4];
    const float* kw2      = (const float*)d_in[5];
    const float* kb2      = (const float*)d_in[6];
    const float* eiw      = (const float*)d_in[7];
    const float* ow1      = (const float*)d_in[8];
    const float* ob1      = (const float*)d_in[9];
    const float* ow2      = (const float*)d_in[10];
    const float* ob2      = (const float*)d_in[11];
    float* out = (float*)d_out;

    static int configured = 0;
    if (!configured) {
        cudaFuncSetAttribute(k_layer, cudaFuncAttributeMaxDynamicSharedMemorySize, MS_BYTES);
        configured = 1;
    }
    void* xsptr = nullptr;
    cudaGetSymbolAddress(&xsptr, g_xs);

    k_init<<<4096, 256>>>(emb_elec);
    k_prepack<<<NL, 256>>>(kw1, kw2, kb2, ow1, ow2, eiw);
    for (int l = 0; l < NL; ++l) {
        float* xs_out = (l == NL - 1) ? out : (float*)xsptr;
        k_layer<<<NB, 256, MS_BYTES>>>(dists, emb_nuc, kb1, ob1, ob2, l, xs_out);
    }
}